// round 11
// baseline (speedup 1.0000x reference)
#include <cuda_runtime.h>
#include <cstdint>

// Shapes (fixed)
#define N_TOTAL 2048
#define T_DIM   128
#define F_DIM   32
#define K_DIM   32

#define NB      16                 // n per block
#define TC      8                  // t per chunk
#define CHUNKS  16
#define THREADS 256                // 8 warps: 2 n-groups x 4 k-groups
#define NBLOCKS (N_TOTAL / NB)     // 128
#define NSLOTS  4

#define XBUF_FLOATS (NB * TC * F_DIM)      // 4096 (16KB/slot)
#define CBUF_FLOATS (K_DIM * TC * F_DIM)   // 8192 (32KB/slot)
#define XBYTES      (XBUF_FLOATS * 4)
#define CBYTES      (CBUF_FLOATS * 4)
#define SMEM_BYTES  (NSLOTS * (XBYTES + CBYTES))   // 192KB

typedef unsigned long long u64;
struct alignas(16) f4 { u64 a, b; };               // packed 4 x f32 (2 x f32x2)

__device__ float g_c2[K_DIM * F_DIM];              // precomputed sum_t c^2, [k][f]

__device__ __forceinline__ void cp_async16(uint32_t dst, const void* src) {
    asm volatile("cp.async.cg.shared.global [%0], [%1], 16;\n" :: "r"(dst), "l"(src));
}
__device__ __forceinline__ void cp_commit() {
    asm volatile("cp.async.commit_group;\n" ::: "memory");
}
__device__ __forceinline__ void cp_wait2() {
    asm volatile("cp.async.wait_group 2;\n" ::: "memory");
}
__device__ __forceinline__ void ffma2(u64& d, u64 a, u64 b, u64 c) {
    asm("fma.rn.f32x2 %0, %1, %2, %3;" : "=l"(d) : "l"(a), "l"(b), "l"(c));
}
__device__ __forceinline__ u64 fadd2(u64 a, u64 b) {
    u64 d; asm("add.rn.f32x2 %0, %1, %2;" : "=l"(d) : "l"(a), "l"(b)); return d;
}
__device__ __forceinline__ float fsqrt_approx(float v) {
    float r; asm("sqrt.approx.f32 %0, %1;" : "=f"(r) : "f"(v)); return r;
}
__device__ __forceinline__ float frcp_approx(float v) {
    float r; asm("rcp.approx.f32 %0, %1;" : "=f"(r) : "f"(v)); return r;
}
__device__ __forceinline__ float lo32(u64 v) { return __uint_as_float((unsigned)v); }
__device__ __forceinline__ float hi32(u64 v) { return __uint_as_float((unsigned)(v >> 32)); }

#define NEG2_PACKED 0xC0000000C0000000ULL

// ================= Kernel 0: c^2 = sum_t clusters^2, per (k, f) ===============
extern "C" __global__ void __launch_bounds__(128, 1)
ts_c2_kernel(const float* __restrict__ clusters) {
    __shared__ float4 red[128];
    const int k    = blockIdx.x;            // 32 blocks
    const int fq   = threadIdx.x & 7;       // f-quad
    const int tseg = threadIdx.x >> 3;      // 16 segments of 8 t
    float4 s = make_float4(0.f, 0.f, 0.f, 0.f);
    const float* base = clusters + ((size_t)k * T_DIM + tseg * 8) * F_DIM + fq * 4;
    #pragma unroll
    for (int t = 0; t < 8; t++) {
        float4 v = *(const float4*)(base + t * F_DIM);
        s.x = fmaf(v.x, v.x, s.x); s.y = fmaf(v.y, v.y, s.y);
        s.z = fmaf(v.z, v.z, s.z); s.w = fmaf(v.w, v.w, s.w);
    }
    red[threadIdx.x] = s;
    __syncthreads();
    if (threadIdx.x < 8) {
        float4 acc = red[threadIdx.x];
        #pragma unroll
        for (int g = 1; g < 16; g++) {
            float4 b = red[g * 8 + threadIdx.x];
            acc.x += b.x; acc.y += b.y; acc.z += b.z; acc.w += b.w;
        }
        *(float4*)&g_c2[k * F_DIM + threadIdx.x * 4] = acc;
    }
}

// ================= Kernel 1: main distance GEMM ===============================
extern "C" __global__ void __launch_bounds__(THREADS, 1)
ts_clustering_kernel(const float* __restrict__ x,
                     const float* __restrict__ clusters,
                     float* __restrict__ out) {
    extern __shared__ float smem[];
    const uint32_t smem_u32 = (uint32_t)__cvta_generic_to_shared(smem);

    const int tid  = threadIdx.x;
    const int lane = tid & 31;
    const int w    = tid >> 5;          // 0..7
    const int wn   = w & 1;             // n-group (8 n each)
    const int wk   = w >> 1;            // k-group (8 k each)
    const int fq   = lane & 7;          // f-quad 0..7  (f = 4fq..4fq+3)
    const int nsub = lane >> 3;         // n-quarter 0..3 (2 n each)
    const int nBase = blockIdx.x * NB;

    const int base_n = wn * 8 + nsub * 2;   // 2 n's per lane
    const int base_k = wk * 8;              // 8 k's per warp

    // ---- compressed prefetch pointers (r-stride is linear: +65536B) ----------
    const char* xsrc = (const char*)x + ((size_t)(nBase + (tid >> 6))) * 16384
                     + (size_t)(tid & 63) * 16;
    const char* csrc = (const char*)clusters + ((size_t)(tid >> 6)) * 16384
                     + (size_t)(tid & 63) * 16;
    const uint32_t xdst = smem_u32 + (uint32_t)tid * 16;
    const uint32_t cdst = smem_u32 + (uint32_t)(NSLOTS * XBYTES) + (uint32_t)tid * 16;
    const int STEP = TC * F_DIM * 4;   // 1KB chunk advance

    auto prefetch = [&](int slot) {
        const uint32_t xo = (uint32_t)slot * XBYTES;
        const uint32_t co = (uint32_t)slot * CBYTES;
        #pragma unroll
        for (int r = 0; r < 4; r++)
            cp_async16(xdst + xo + (uint32_t)r * 4096u, xsrc + (size_t)r * 65536);
        #pragma unroll
        for (int r = 0; r < 8; r++)
            cp_async16(cdst + co + (uint32_t)r * 4096u, csrc + (size_t)r * 65536);
        xsrc += STEP; csrc += STEP;
    };

    // ---- accumulators (all static indexing) ----------------------------------
    f4 acc[2][8];
    #pragma unroll
    for (int i = 0; i < 2; i++)
        #pragma unroll
        for (int j = 0; j < 8; j++) { acc[i][j].a = 0ULL; acc[i][j].b = 0ULL; }
    f4 sx2p[2];
    sx2p[0].a = sx2p[0].b = sx2p[1].a = sx2p[1].b = 0ULL;   // x^2, (t&3)==wk phase

    prefetch(0); cp_commit();
    prefetch(1); cp_commit();

    #pragma unroll 4
    for (int ci = 0; ci < CHUNKS; ci++) {
        if (ci + 2 < CHUNKS) prefetch((ci + 2) & 3);
        cp_commit();            // uniform group count (empty tail groups)
        cp_wait2();             // chunk ci complete (2 newer may be in flight)
        __syncthreads();        // cross-thread visibility; also protects slots

        const float* xs = smem + (ci & 3) * XBUF_FLOATS;                        // [NB][TC][F]
        const float* cs = smem + NSLOTS * XBUF_FLOATS + (ci & 3) * CBUF_FLOATS; // [K][TC][F]
        const float* xp = xs + (base_n * TC) * F_DIM + 4 * fq;
        const float* cq = cs + (base_k * TC) * F_DIM + 4 * fq;

        // software-pipelined t-loop: operands double-buffered by parity
        f4 xrb[2][2], crb[2][8];
        #pragma unroll
        for (int i = 0; i < 2; i++) xrb[0][i] = *(const f4*)(xp + (i * TC) * F_DIM);
        #pragma unroll
        for (int j = 0; j < 8; j++) crb[0][j] = *(const f4*)(cq + (j * TC) * F_DIM);

        #pragma unroll
        for (int t = 0; t < TC; t++) {
            const int cur = t & 1, nxt = cur ^ 1;
            if (t + 1 < TC) {
                #pragma unroll
                for (int i = 0; i < 2; i++)
                    xrb[nxt][i] = *(const f4*)(xp + (i * TC + t + 1) * F_DIM);
                #pragma unroll
                for (int j = 0; j < 8; j++)
                    crb[nxt][j] = *(const f4*)(cq + (j * TC + t + 1) * F_DIM);
            }
            #pragma unroll
            for (int i = 0; i < 2; i++)
                #pragma unroll
                for (int j = 0; j < 8; j++) {
                    ffma2(acc[i][j].a, xrb[cur][i].a, crb[cur][j].a, acc[i][j].a);
                    ffma2(acc[i][j].b, xrb[cur][i].b, crb[cur][j].b, acc[i][j].b);
                }
            if ((t & 3) == wk) {
                #pragma unroll
                for (int i = 0; i < 2; i++) {
                    ffma2(sx2p[i].a, xrb[cur][i].a, xrb[cur][i].a, sx2p[i].a);
                    ffma2(sx2p[i].b, xrb[cur][i].b, xrb[cur][i].b, sx2p[i].b);
                }
            }
        }
        // single barrier per chunk (at top of next iter) protects slot reuse:
        // prefetch(ci+3) overwrites slot (ci-1)&3, last read in iter ci-1.
    }

    // ---- epilogue ------------------------------------------------------------
    __syncthreads();
    float* x2part = smem;            // [4 wk][16 n][8 fq] f4 = 2048 floats (8KB)
    float* dsts   = smem + 2048;     // [16 n][32 k] f32 (2KB)

    #pragma unroll
    for (int i = 0; i < 2; i++) {
        int n = base_n + i;
        *(f4*)&x2part[4 * ((wk * 16 + n) * 8 + fq)] = sx2p[i];
    }
    __syncthreads();

    // c2 from precomputed global (L2-hot, 4KB shared by all blocks)
    f4 c2p[8];
    #pragma unroll
    for (int j = 0; j < 8; j++)
        c2p[j] = *(const f4*)&g_c2[(base_k + j) * F_DIM + 4 * fq];

    #pragma unroll
    for (int i = 0; i < 2; i++) {
        int n = base_n + i;
        f4 x2t;
        x2t.a = fadd2(fadd2(((const f4*)&x2part[4 * ((0 * 16 + n) * 8 + fq)])->a,
                            ((const f4*)&x2part[4 * ((1 * 16 + n) * 8 + fq)])->a),
                      fadd2(((const f4*)&x2part[4 * ((2 * 16 + n) * 8 + fq)])->a,
                            ((const f4*)&x2part[4 * ((3 * 16 + n) * 8 + fq)])->a));
        x2t.b = fadd2(fadd2(((const f4*)&x2part[4 * ((0 * 16 + n) * 8 + fq)])->b,
                            ((const f4*)&x2part[4 * ((1 * 16 + n) * 8 + fq)])->b),
                      fadd2(((const f4*)&x2part[4 * ((2 * 16 + n) * 8 + fq)])->b,
                            ((const f4*)&x2part[4 * ((3 * 16 + n) * 8 + fq)])->b));
        #pragma unroll
        for (int j = 0; j < 8; j++) {
            u64 sa = fadd2(x2t.a, c2p[j].a);
            u64 sb = fadd2(x2t.b, c2p[j].b);
            u64 qa, qb;
            ffma2(qa, acc[i][j].a, NEG2_PACKED, sa);   // x2 + c2 - 2*xc
            ffma2(qb, acc[i][j].b, NEG2_PACKED, sb);
            float ed = fsqrt_approx(fmaxf(lo32(qa), 0.0f))
                     + fsqrt_approx(fmaxf(hi32(qa), 0.0f))
                     + fsqrt_approx(fmaxf(lo32(qb), 0.0f))
                     + fsqrt_approx(fmaxf(hi32(qb), 0.0f));
            #pragma unroll
            for (int off = 4; off > 0; off >>= 1)      // reduce 8 f-quads
                ed += __shfl_xor_sync(0xffffffffu, ed, off);
            if (fq == 0)                                // 4 writer lanes, distinct n
                dsts[n * K_DIM + (base_k + j)] = ed;
        }
    }
    __syncthreads();

    // ---- Student-t + per-n normalization: warp w handles n = w, w+8 ----------
    #pragma unroll
    for (int n = w; n < NB; n += 8) {
        float d = dsts[n * K_DIM + lane];
        float q = frcp_approx(fmaf(d, d, 1.0f));       // alpha = 1
        float sum = q;
        #pragma unroll
        for (int off = 16; off > 0; off >>= 1)
            sum += __shfl_xor_sync(0xffffffffu, sum, off);
        out[(size_t)(nBase + n) * K_DIM + lane] = q * frcp_approx(sum);
    }
}

extern "C" void kernel_launch(void* const* d_in, const int* in_sizes, int n_in,
                              void* d_out, int out_size) {
    const float* x        = (const float*)d_in[0];   // (2048, 128, 32)
    const float* clusters = (const float*)d_in[1];   // (32, 128, 32)
    float* out            = (float*)d_out;           // (2048, 32)
    (void)in_sizes; (void)n_in; (void)out_size;

    ts_c2_kernel<<<K_DIM, 128>>>(clusters);
    cudaFuncSetAttribute(ts_clustering_kernel,
                         cudaFuncAttributeMaxDynamicSharedMemorySize, SMEM_BYTES);
    ts_clustering_kernel<<<NBLOCKS, THREADS, SMEM_BYTES>>>(x, clusters, out);
}

// round 12
// speedup vs baseline: 1.2126x; 1.2126x over previous
#include <cuda_runtime.h>
#include <cstdint>

// Shapes (fixed)
#define N_TOTAL 2048
#define T_DIM   128
#define F_DIM   32
#define K_DIM   32

#define NB      16                 // n per block
#define TC      8                  // t per chunk
#define CHUNKS  (T_DIM / TC)       // 16
#define THREADS 256                // 8 warps: 2 n-groups x 4 k-groups
#define NBLOCKS (N_TOTAL / NB)     // 128
#define NSLOTS  4

#define XBUF_FLOATS (NB * TC * F_DIM)      // 4096 (16KB/slot)
#define CBUF_FLOATS (K_DIM * TC * F_DIM)   // 8192 (32KB/slot)
#define XBYTES      (XBUF_FLOATS * 4)
#define CBYTES      (CBUF_FLOATS * 4)
#define SMEM_BYTES  (NSLOTS * (XBYTES + CBYTES))   // 192KB

typedef unsigned long long u64;

__device__ float g_c2[K_DIM * F_DIM];   // sum_t c^2 per (k, f) — 4KB, L2-hot

__device__ __forceinline__ void cp_async16(uint32_t dst, const void* src) {
    asm volatile("cp.async.cg.shared.global [%0], [%1], 16;\n" :: "r"(dst), "l"(src));
}
__device__ __forceinline__ void cp_commit() {
    asm volatile("cp.async.commit_group;\n" ::: "memory");
}
__device__ __forceinline__ void cp_wait2() {
    asm volatile("cp.async.wait_group 2;\n" ::: "memory");
}
__device__ __forceinline__ void ffma2(u64& d, u64 a, u64 b, u64 c) {
    asm("fma.rn.f32x2 %0, %1, %2, %3;" : "=l"(d) : "l"(a), "l"(b), "l"(c));
}
__device__ __forceinline__ u64 fadd2(u64 a, u64 b) {
    u64 d; asm("add.rn.f32x2 %0, %1, %2;" : "=l"(d) : "l"(a), "l"(b)); return d;
}
__device__ __forceinline__ float fsqrt_approx(float v) {
    float r; asm("sqrt.approx.f32 %0, %1;" : "=f"(r) : "f"(v)); return r;
}
__device__ __forceinline__ float frcp_approx(float v) {
    float r; asm("rcp.approx.f32 %0, %1;" : "=f"(r) : "f"(v)); return r;
}
__device__ __forceinline__ u64 lds64(const float* p) {
    return *reinterpret_cast<const u64*>(p);
}
__device__ __forceinline__ float lo32(u64 v) { return __uint_as_float((unsigned)v); }
__device__ __forceinline__ float hi32(u64 v) { return __uint_as_float((unsigned)(v >> 32)); }

#define NEG2_PACKED 0xC0000000C0000000ULL

// ================= Kernel 0: c^2 = sum_t clusters^2, per (k, f) ===============
extern "C" __global__ void __launch_bounds__(128, 1)
ts_c2_kernel(const float* __restrict__ clusters) {
    __shared__ float4 red[128];
    const int k    = blockIdx.x;            // 32 blocks
    const int fq   = threadIdx.x & 7;       // f-quad
    const int tseg = threadIdx.x >> 3;      // 16 segments of 8 t
    float4 s = make_float4(0.f, 0.f, 0.f, 0.f);
    const float* base = clusters + ((size_t)k * T_DIM + tseg * 8) * F_DIM + fq * 4;
    #pragma unroll
    for (int t = 0; t < 8; t++) {
        float4 v = *(const float4*)(base + t * F_DIM);
        s.x = fmaf(v.x, v.x, s.x); s.y = fmaf(v.y, v.y, s.y);
        s.z = fmaf(v.z, v.z, s.z); s.w = fmaf(v.w, v.w, s.w);
    }
    red[threadIdx.x] = s;
    __syncthreads();
    if (threadIdx.x < 8) {
        float4 acc = red[threadIdx.x];
        #pragma unroll
        for (int g = 1; g < 16; g++) {
            float4 b = red[g * 8 + threadIdx.x];
            acc.x += b.x; acc.y += b.y; acc.z += b.z; acc.w += b.w;
        }
        *(float4*)&g_c2[k * F_DIM + threadIdx.x * 4] = acc;
    }
}

// ================= Kernel 1: main distance GEMM (R8 core, c2 removed) =========
extern "C" __global__ void __launch_bounds__(THREADS, 1)
ts_clustering_kernel(const float* __restrict__ x,
                     const float* __restrict__ clusters,
                     float* __restrict__ out) {
    extern __shared__ float smem[];
    const uint32_t smem_u32 = (uint32_t)__cvta_generic_to_shared(smem);

    const int tid  = threadIdx.x;
    const int lane = tid & 31;
    const int w    = tid >> 5;          // 0..7
    const int wn   = w & 1;             // n-group: 8 n each
    const int wk   = w >> 1;            // k-group: 8 k each
    const int fp   = lane & 15;         // f-pair 0..15
    const int nsub = lane >> 4;         // n-half
    const int nBase = blockIdx.x * NB;

    const int base_n = wn * 8 + nsub * 4;   // 4 n's per lane
    const int base_k = wk * 8;              // 8 k's per warp

    // ---- persistent prefetch pointers (advance 1KB per chunk) ----------------
    const char* xsrc0; const char* xsrc1; const char* xsrc2; const char* xsrc3;
    uint32_t    xdst0, xdst1, xdst2, xdst3;
    {
        int i0 = tid, i1 = tid + 256, i2 = tid + 512, i3 = tid + 768;
        xsrc0 = (const char*)x + ((size_t)(nBase + (i0 >> 6)) * T_DIM) * (F_DIM * 4) + (size_t)(i0 & 63) * 16;
        xsrc1 = (const char*)x + ((size_t)(nBase + (i1 >> 6)) * T_DIM) * (F_DIM * 4) + (size_t)(i1 & 63) * 16;
        xsrc2 = (const char*)x + ((size_t)(nBase + (i2 >> 6)) * T_DIM) * (F_DIM * 4) + (size_t)(i2 & 63) * 16;
        xsrc3 = (const char*)x + ((size_t)(nBase + (i3 >> 6)) * T_DIM) * (F_DIM * 4) + (size_t)(i3 & 63) * 16;
        xdst0 = smem_u32 + (uint32_t)i0 * 16;
        xdst1 = smem_u32 + (uint32_t)i1 * 16;
        xdst2 = smem_u32 + (uint32_t)i2 * 16;
        xdst3 = smem_u32 + (uint32_t)i3 * 16;
    }
    const char* csrc[8];
    uint32_t    cdst[8];
    #pragma unroll
    for (int r = 0; r < 8; r++) {
        int idx = tid + r * 256;
        csrc[r] = (const char*)clusters + ((size_t)(idx >> 6) * T_DIM) * (F_DIM * 4)
                + (size_t)(idx & 63) * 16;
        cdst[r] = smem_u32 + (uint32_t)(NSLOTS * XBYTES) + (uint32_t)idx * 16;
    }
    const int STEP = TC * F_DIM * 4;   // 1KB per chunk advance

    auto prefetch = [&](int slot) {
        const uint32_t xo = (uint32_t)slot * XBYTES;
        const uint32_t co = (uint32_t)slot * CBYTES;
        cp_async16(xdst0 + xo, xsrc0); xsrc0 += STEP;
        cp_async16(xdst1 + xo, xsrc1); xsrc1 += STEP;
        cp_async16(xdst2 + xo, xsrc2); xsrc2 += STEP;
        cp_async16(xdst3 + xo, xsrc3); xsrc3 += STEP;
        #pragma unroll
        for (int r = 0; r < 8; r++) { cp_async16(cdst[r] + co, csrc[r]); csrc[r] += STEP; }
    };

    // ---- accumulators (all static indexing) ----------------------------------
    u64 acc[4][8];
    #pragma unroll
    for (int i = 0; i < 4; i++)
        #pragma unroll
        for (int j = 0; j < 8; j++) acc[i][j] = 0ULL;
    u64 sx2p[4] = {0ULL, 0ULL, 0ULL, 0ULL};    // x^2 partials, phase (t&3)==wk

    prefetch(0); cp_commit();
    prefetch(1); cp_commit();

    #pragma unroll 4
    for (int ci = 0; ci < CHUNKS; ci++) {
        if (ci + 2 < CHUNKS) prefetch((ci + 2) & 3);
        cp_commit();            // uniform group count (empty tail groups)
        cp_wait2();             // chunk ci complete (2 newer may be in flight)
        __syncthreads();        // visibility + slot-reuse protection

        const float* xs = smem + (ci & 3) * XBUF_FLOATS;                        // [NB][TC][F]
        const float* cs = smem + NSLOTS * XBUF_FLOATS + (ci & 3) * CBUF_FLOATS; // [K][TC][F]
        const float* xp = xs + (base_n * TC) * F_DIM + 2 * fp;
        const float* cp = cs + (base_k * TC) * F_DIM + 2 * fp;

        #pragma unroll
        for (int t = 0; t < TC; t++) {
            u64 xr[4], cr[8];
            #pragma unroll
            for (int i = 0; i < 4; i++)
                xr[i] = lds64(xp + (i * TC + t) * F_DIM);
            #pragma unroll
            for (int j = 0; j < 8; j++)
                cr[j] = lds64(cp + (j * TC + t) * F_DIM);
            #pragma unroll
            for (int i = 0; i < 4; i++)
                #pragma unroll
                for (int j = 0; j < 8; j++)
                    ffma2(acc[i][j], xr[i], cr[j], acc[i][j]);
            if ((t & 3) == wk) {
                #pragma unroll
                for (int i = 0; i < 4; i++) ffma2(sx2p[i], xr[i], xr[i], sx2p[i]);
            }
        }
        // single barrier per chunk (top of next iter) protects slot reuse:
        // prefetch(ci+3) overwrites slot (ci-1)&3, last read in iter ci-1.
    }

    // ---- epilogue ------------------------------------------------------------
    __syncthreads();
    float* x2part = smem;            // [4 wk][16 n][16 fp] pairs = 2048 floats
    float* dsts   = smem + 2048;     // [16 n][32 k] = 512 floats

    #pragma unroll
    for (int i = 0; i < 4; i++) {
        int n = base_n + i;
        *reinterpret_cast<u64*>(&x2part[2 * ((wk * 16 + n) * 16 + fp)]) = sx2p[i];
    }
    __syncthreads();

    // c2 from precomputed global (4KB, L2-hot across all 128 CTAs)
    u64 c2p[8];
    #pragma unroll
    for (int j = 0; j < 8; j++)
        c2p[j] = *(const u64*)&g_c2[(base_k + j) * F_DIM + 2 * fp];

    #pragma unroll
    for (int i = 0; i < 4; i++) {
        int n = base_n + i;
        u64 x2p = fadd2(fadd2(lds64(&x2part[2 * ((0 * 16 + n) * 16 + fp)]),
                              lds64(&x2part[2 * ((1 * 16 + n) * 16 + fp)])),
                        fadd2(lds64(&x2part[2 * ((2 * 16 + n) * 16 + fp)]),
                              lds64(&x2part[2 * ((3 * 16 + n) * 16 + fp)])));
        #pragma unroll
        for (int j = 0; j < 8; j++) {
            u64 s  = fadd2(x2p, c2p[j]);
            u64 sq;
            ffma2(sq, acc[i][j], NEG2_PACKED, s);   // x2 + c2 - 2*xc (both f's)
            float ed = fsqrt_approx(fmaxf(lo32(sq), 0.0f))
                     + fsqrt_approx(fmaxf(hi32(sq), 0.0f));
            #pragma unroll
            for (int off = 8; off > 0; off >>= 1)   // reduce 16 f-pairs per half
                ed += __shfl_xor_sync(0xffffffffu, ed, off);
            if (fp == 0)                             // lanes 0 & 16: distinct n
                dsts[n * K_DIM + (base_k + j)] = ed;
        }
    }
    __syncthreads();

    // ---- Student-t + per-n normalization: warp w handles n = w, w+8 ----------
    #pragma unroll
    for (int n = w; n < NB; n += 8) {
        float d = dsts[n * K_DIM + lane];
        float q = frcp_approx(fmaf(d, d, 1.0f));     // alpha = 1
        float sum = q;
        #pragma unroll
        for (int off = 16; off > 0; off >>= 1)
            sum += __shfl_xor_sync(0xffffffffu, sum, off);
        out[(size_t)(nBase + n) * K_DIM + lane] = q * frcp_approx(sum);
    }
}

extern "C" void kernel_launch(void* const* d_in, const int* in_sizes, int n_in,
                              void* d_out, int out_size) {
    const float* x        = (const float*)d_in[0];   // (2048, 128, 32)
    const float* clusters = (const float*)d_in[1];   // (32, 128, 32)
    float* out            = (float*)d_out;           // (2048, 32)
    (void)in_sizes; (void)n_in; (void)out_size;

    ts_c2_kernel<<<K_DIM, 128>>>(clusters);
    cudaFuncSetAttribute(ts_clustering_kernel,
                         cudaFuncAttributeMaxDynamicSharedMemorySize, SMEM_BYTES);
    ts_clustering_kernel<<<NBLOCKS, THREADS, SMEM_BYTES>>>(x, clusters, out);
}

// round 13
// speedup vs baseline: 1.2140x; 1.0012x over previous
#include <cuda_runtime.h>
#include <cstdint>

// Shapes (fixed)
#define N_TOTAL 2048
#define T_DIM   128
#define F_DIM   32
#define K_DIM   32

#define NB      16                 // n per block
#define TC      8                  // t per chunk
#define CHUNKS  (T_DIM / TC)       // 16
#define THREADS 256                // 8 warps: 2 n-groups x 4 k-groups
#define NBLOCKS (N_TOTAL / NB)     // 128
#define NSLOTS  4

#define XBUF_FLOATS (NB * TC * F_DIM)      // 4096 (16KB/slot)
#define CBUF_FLOATS (K_DIM * TC * F_DIM)   // 8192 (32KB/slot)
#define XBYTES      (XBUF_FLOATS * 4)
#define CBYTES      (CBUF_FLOATS * 4)
#define SMEM_BYTES  (NSLOTS * (XBYTES + CBYTES))   // 192KB

typedef unsigned long long u64;

__device__ __forceinline__ void cp_async16(uint32_t dst, const void* src) {
    asm volatile("cp.async.cg.shared.global [%0], [%1], 16;\n" :: "r"(dst), "l"(src));
}
__device__ __forceinline__ void cp_commit() {
    asm volatile("cp.async.commit_group;\n" ::: "memory");
}
__device__ __forceinline__ void cp_wait2() {
    asm volatile("cp.async.wait_group 2;\n" ::: "memory");
}
__device__ __forceinline__ void ffma2(u64& d, u64 a, u64 b, u64 c) {
    asm("fma.rn.f32x2 %0, %1, %2, %3;" : "=l"(d) : "l"(a), "l"(b), "l"(c));
}
__device__ __forceinline__ u64 fadd2(u64 a, u64 b) {
    u64 d; asm("add.rn.f32x2 %0, %1, %2;" : "=l"(d) : "l"(a), "l"(b)); return d;
}
__device__ __forceinline__ float fsqrt_approx(float v) {
    float r; asm("sqrt.approx.f32 %0, %1;" : "=f"(r) : "f"(v)); return r;
}
__device__ __forceinline__ float frcp_approx(float v) {
    float r; asm("rcp.approx.f32 %0, %1;" : "=f"(r) : "f"(v)); return r;
}
__device__ __forceinline__ u64 lds64(const float* p) {
    return *reinterpret_cast<const u64*>(p);
}
__device__ __forceinline__ float lo32(u64 v) { return __uint_as_float((unsigned)v); }
__device__ __forceinline__ float hi32(u64 v) { return __uint_as_float((unsigned)(v >> 32)); }

#define NEG2_PACKED 0xC0000000C0000000ULL

extern "C" __global__ void __launch_bounds__(THREADS, 1)
ts_clustering_kernel(const float* __restrict__ x,
                     const float* __restrict__ clusters,
                     float* __restrict__ out) {
    extern __shared__ float smem[];
    const uint32_t smem_u32 = (uint32_t)__cvta_generic_to_shared(smem);

    const int tid  = threadIdx.x;
    const int lane = tid & 31;
    const int w    = tid >> 5;          // 0..7
    const int wn   = w & 1;             // n-group: 8 n each
    const int wk   = w >> 1;            // k-group: 8 k each
    const int fp   = lane & 15;         // f-pair 0..15
    const int nsub = lane >> 4;         // n-half
    const int nBase = blockIdx.x * NB;

    const int base_n = wn * 8 + nsub * 4;   // 4 n's per lane
    const int base_k = wk * 8;              // 8 k's per warp

    // ---- compressed prefetch addressing --------------------------------------
    // idx = tid + r*256 -> row = (tid>>6) + 4r, rem = tid&63 (invariant in r)
    // => gmem stride per r = 4 rows * 16KB = 65536B; smem stride per r = 4096B
    const char* xsrc = (const char*)x
        + ((size_t)(nBase + (tid >> 6)) * T_DIM) * (F_DIM * 4) + (size_t)(tid & 63) * 16;
    const char* csrc = (const char*)clusters
        + ((size_t)(tid >> 6) * T_DIM) * (F_DIM * 4) + (size_t)(tid & 63) * 16;
    const uint32_t xdst = smem_u32 + (uint32_t)tid * 16;
    const uint32_t cdst = smem_u32 + (uint32_t)(NSLOTS * XBYTES) + (uint32_t)tid * 16;
    const int STEP = TC * F_DIM * 4;   // 1KB per chunk advance

    auto prefetch = [&](int slot) {
        const uint32_t xo = (uint32_t)slot * XBYTES;
        const uint32_t co = (uint32_t)slot * CBYTES;
        #pragma unroll
        for (int r = 0; r < 4; r++)      // x: 1024 x 16B
            cp_async16(xdst + xo + (uint32_t)(r * 4096), xsrc + (size_t)r * 65536);
        #pragma unroll
        for (int r = 0; r < 8; r++)      // c: 2048 x 16B
            cp_async16(cdst + co + (uint32_t)(r * 4096), csrc + (size_t)r * 65536);
        xsrc += STEP; csrc += STEP;
    };

    // ---- accumulators (all static indexing) ----------------------------------
    u64 acc[4][8];
    #pragma unroll
    for (int i = 0; i < 4; i++)
        #pragma unroll
        for (int j = 0; j < 8; j++) acc[i][j] = 0ULL;
    u64 sx2p[4] = {0ULL, 0ULL, 0ULL, 0ULL};                   // (t&3)==wk phase
    u64 sc2p[8] = {0ULL,0ULL,0ULL,0ULL,0ULL,0ULL,0ULL,0ULL}; // (t&1)==wn phase

    prefetch(0); cp_commit();
    prefetch(1); cp_commit();

    #pragma unroll 2
    for (int ci = 0; ci < CHUNKS; ci++) {
        if (ci + 2 < CHUNKS) prefetch((ci + 2) & 3);
        cp_commit();            // uniform group count (empty tail groups)
        cp_wait2();             // chunk ci complete (2 newer may be in flight)
        __syncthreads();        // visibility + slot-reuse protection

        const float* xs = smem + (ci & 3) * XBUF_FLOATS;                        // [NB][TC][F]
        const float* cs = smem + NSLOTS * XBUF_FLOATS + (ci & 3) * CBUF_FLOATS; // [K][TC][F]
        const float* xp = xs + (base_n * TC) * F_DIM + 2 * fp;
        const float* cp = cs + (base_k * TC) * F_DIM + 2 * fp;

        #pragma unroll
        for (int t = 0; t < TC; t++) {
            u64 xr[4], cr[8];
            #pragma unroll
            for (int i = 0; i < 4; i++)
                xr[i] = lds64(xp + (i * TC + t) * F_DIM);
            #pragma unroll
            for (int j = 0; j < 8; j++)
                cr[j] = lds64(cp + (j * TC + t) * F_DIM);
            #pragma unroll
            for (int i = 0; i < 4; i++)
                #pragma unroll
                for (int j = 0; j < 8; j++)
                    ffma2(acc[i][j], xr[i], cr[j], acc[i][j]);
            if ((t & 3) == wk) {
                #pragma unroll
                for (int i = 0; i < 4; i++) ffma2(sx2p[i], xr[i], xr[i], sx2p[i]);
            }
            if ((t & 1) == wn) {
                #pragma unroll
                for (int j = 0; j < 8; j++) ffma2(sc2p[j], cr[j], cr[j], sc2p[j]);
            }
        }
        // single barrier per chunk (top of next iter) protects slot reuse:
        // prefetch(ci+3) overwrites slot (ci-1)&3, last read in iter ci-1.
    }

    // ---- epilogue ------------------------------------------------------------
    __syncthreads();
    float* x2part = smem;            // [4 wk][16 n][16 fp] pairs = 2048 floats
    float* c2part = smem + 2048;     // [2 wn][32 k][16 fp] pairs = 2048 floats
    float* dsts   = smem + 4096;     // [16 n][32 k] = 512 floats

    #pragma unroll
    for (int i = 0; i < 4; i++) {
        int n = base_n + i;
        *reinterpret_cast<u64*>(&x2part[2 * ((wk * 16 + n) * 16 + fp)]) = sx2p[i];
    }
    if (nsub == 0) {                 // both halves hold identical sc2p
        #pragma unroll
        for (int j = 0; j < 8; j++) {
            int k = base_k + j;
            *reinterpret_cast<u64*>(&c2part[2 * ((wn * 32 + k) * 16 + fp)]) = sc2p[j];
        }
    }
    __syncthreads();

    u64 c2p[8];
    #pragma unroll
    for (int j = 0; j < 8; j++) {
        int k = base_k + j;
        c2p[j] = fadd2(lds64(&c2part[2 * ((0 * 32 + k) * 16 + fp)]),
                       lds64(&c2part[2 * ((1 * 32 + k) * 16 + fp)]));
    }

    #pragma unroll
    for (int i = 0; i < 4; i++) {
        int n = base_n + i;
        u64 x2p = fadd2(fadd2(lds64(&x2part[2 * ((0 * 16 + n) * 16 + fp)]),
                              lds64(&x2part[2 * ((1 * 16 + n) * 16 + fp)])),
                        fadd2(lds64(&x2part[2 * ((2 * 16 + n) * 16 + fp)]),
                              lds64(&x2part[2 * ((3 * 16 + n) * 16 + fp)])));
        #pragma unroll
        for (int j = 0; j < 8; j++) {
            u64 s  = fadd2(x2p, c2p[j]);
            u64 sq;
            ffma2(sq, acc[i][j], NEG2_PACKED, s);   // x2 + c2 - 2*xc (both f's)
            float ed = fsqrt_approx(fmaxf(lo32(sq), 0.0f))
                     + fsqrt_approx(fmaxf(hi32(sq), 0.0f));
            #pragma unroll
            for (int off = 8; off > 0; off >>= 1)   // reduce 16 f-pairs per half
                ed += __shfl_xor_sync(0xffffffffu, ed, off);
            if (fp == 0)                             // lanes 0 & 16: distinct n
                dsts[n * K_DIM + (base_k + j)] = ed;
        }
    }
    __syncthreads();

    // ---- Student-t + per-n normalization: warp w handles n = w, w+8 ----------
    #pragma unroll
    for (int n = w; n < NB; n += 8) {
        float d = dsts[n * K_DIM + lane];
        float q = frcp_approx(fmaf(d, d, 1.0f));     // alpha = 1
        float sum = q;
        #pragma unroll
        for (int off = 16; off > 0; off >>= 1)
            sum += __shfl_xor_sync(0xffffffffu, sum, off);
        out[(size_t)(nBase + n) * K_DIM + lane] = q * frcp_approx(sum);
    }
}

extern "C" void kernel_launch(void* const* d_in, const int* in_sizes, int n_in,
                              void* d_out, int out_size) {
    const float* x        = (const float*)d_in[0];   // (2048, 128, 32)
    const float* clusters = (const float*)d_in[1];   // (32, 128, 32)
    float* out            = (float*)d_out;           // (2048, 32)
    (void)in_sizes; (void)n_in; (void)out_size;

    cudaFuncSetAttribute(ts_clustering_kernel,
                         cudaFuncAttributeMaxDynamicSharedMemorySize, SMEM_BYTES);
    ts_clustering_kernel<<<NBLOCKS, THREADS, SMEM_BYTES>>>(x, clusters, out);
}